// round 1
// baseline (speedup 1.0000x reference)
#include <cuda_runtime.h>
#include <math.h>

#define NR 8192
#define D  512
#define SCALE 0.1f

// Scratch (allocation-free rule: __device__ globals)
__device__ float g_E[(size_t)NR * NR];      // 256 MB: E = exp(sim - 1)
__device__ float g_xn[(size_t)NR * D];      // 16 MB: row-normalized x
__device__ float g_xneg[(size_t)NR * D];    // 16 MB
__device__ float g_invr[NR];                // 32 KB

__device__ __forceinline__ float warpReduceSum(float v) {
#pragma unroll
    for (int o = 16; o > 0; o >>= 1) v += __shfl_xor_sync(0xffffffffu, v, o);
    return v;
}

// ---------------- prep: L2-normalize rows ----------------
__global__ void prep_kernel(const float* __restrict__ x) {
    __shared__ float sred[4];
    int row = blockIdx.x;
    int t = threadIdx.x;  // 128 threads, one float4 each
    float4 a = ((const float4*)(x + (size_t)row * D))[t];
    float ss = a.x * a.x + a.y * a.y + a.z * a.z + a.w * a.w;
    ss = warpReduceSum(ss);
    if ((t & 31) == 0) sred[t >> 5] = ss;
    __syncthreads();
    float tot = sred[0] + sred[1] + sred[2] + sred[3];
    float inv = 1.0f / fmaxf(sqrtf(tot), 1e-12f);
    float4 o = make_float4(a.x * inv, a.y * inv, a.z * inv, a.w * inv);
    ((float4*)g_xn)[(size_t)row * (D / 4) + t] = o;
}

// ---------------- GEMM1: E = exp(xn @ xn^T - 1), upper triangle + mirror ----------------
__global__ void __launch_bounds__(256, 2) gemm1_kernel() {
    int bj = blockIdx.x, bi = blockIdx.y;
    if (bi > bj) return;

    __shared__ float As[16][128];
    __shared__ float Bs[16][128];

    int t = threadIdx.x;
    int tx = t & 15, ty = t >> 4;
    int lrow = t >> 1;           // 0..127: smem row this thread loads
    int lkb = (t & 1) * 8;       // 0 or 8: k-offset within tile

    const float* aptr = g_xn + (size_t)(bi * 128 + lrow) * D + lkb;
    const float* bptr = g_xn + (size_t)(bj * 128 + lrow) * D + lkb;

    float acc[8][8];
#pragma unroll
    for (int i = 0; i < 8; i++)
#pragma unroll
        for (int j = 0; j < 8; j++) acc[i][j] = 0.f;

    for (int k0 = 0; k0 < D; k0 += 16) {
        float4 a0 = *(const float4*)(aptr + k0);
        float4 a1 = *(const float4*)(aptr + k0 + 4);
        float4 b0 = *(const float4*)(bptr + k0);
        float4 b1 = *(const float4*)(bptr + k0 + 4);
        As[lkb + 0][lrow] = a0.x; As[lkb + 1][lrow] = a0.y;
        As[lkb + 2][lrow] = a0.z; As[lkb + 3][lrow] = a0.w;
        As[lkb + 4][lrow] = a1.x; As[lkb + 5][lrow] = a1.y;
        As[lkb + 6][lrow] = a1.z; As[lkb + 7][lrow] = a1.w;
        Bs[lkb + 0][lrow] = b0.x; Bs[lkb + 1][lrow] = b0.y;
        Bs[lkb + 2][lrow] = b0.z; Bs[lkb + 3][lrow] = b0.w;
        Bs[lkb + 4][lrow] = b1.x; Bs[lkb + 5][lrow] = b1.y;
        Bs[lkb + 6][lrow] = b1.z; Bs[lkb + 7][lrow] = b1.w;
        __syncthreads();
#pragma unroll
        for (int kk = 0; kk < 16; kk++) {
            float4 xa0 = *(const float4*)&As[kk][ty * 8];
            float4 xa1 = *(const float4*)&As[kk][ty * 8 + 4];
            float4 yb0 = *(const float4*)&Bs[kk][tx * 8];
            float4 yb1 = *(const float4*)&Bs[kk][tx * 8 + 4];
            float av[8] = {xa0.x, xa0.y, xa0.z, xa0.w, xa1.x, xa1.y, xa1.z, xa1.w};
            float bv[8] = {yb0.x, yb0.y, yb0.z, yb0.w, yb1.x, yb1.y, yb1.z, yb1.w};
#pragma unroll
            for (int i = 0; i < 8; i++)
#pragma unroll
                for (int j = 0; j < 8; j++)
                    acc[i][j] = fmaf(av[i], bv[j], acc[i][j]);
        }
        __syncthreads();
    }

    // E = exp(s - 1); row max is exactly 1 (diagonal), so this is the stable softmax numerator
#pragma unroll
    for (int i = 0; i < 8; i++)
#pragma unroll
        for (int j = 0; j < 8; j++) acc[i][j] = expf(acc[i][j] - 1.0f);

    int gr0 = bi * 128 + ty * 8;
    int gc0 = bj * 128 + tx * 8;
#pragma unroll
    for (int i = 0; i < 8; i++) {
        float4 w0 = make_float4(acc[i][0], acc[i][1], acc[i][2], acc[i][3]);
        float4 w1 = make_float4(acc[i][4], acc[i][5], acc[i][6], acc[i][7]);
        *(float4*)(g_E + (size_t)(gr0 + i) * NR + gc0)     = w0;
        *(float4*)(g_E + (size_t)(gr0 + i) * NR + gc0 + 4) = w1;
    }
    if (bi != bj) {  // mirror: E is symmetric
#pragma unroll
        for (int j = 0; j < 8; j++) {
            float4 w0 = make_float4(acc[0][j], acc[1][j], acc[2][j], acc[3][j]);
            float4 w1 = make_float4(acc[4][j], acc[5][j], acc[6][j], acc[7][j]);
            *(float4*)(g_E + (size_t)(gc0 + j) * NR + gr0)     = w0;
            *(float4*)(g_E + (size_t)(gc0 + j) * NR + gr0 + 4) = w1;
        }
    }
}

// ---------------- row sums of E -> invr (deterministic, no atomics) ----------------
__global__ void rowsum_kernel() {
    __shared__ float sred[8];
    int row = blockIdx.x, t = threadIdx.x;  // 256 threads
    const float4* e = (const float4*)(g_E + (size_t)row * NR);
    float s = 0.f;
#pragma unroll
    for (int i = 0; i < 8; i++) {
        float4 v = e[t + 256 * i];
        s += (v.x + v.y) + (v.z + v.w);
    }
    s = warpReduceSum(s);
    if ((t & 31) == 0) sred[t >> 5] = s;
    __syncthreads();
    if (t == 0) {
        float tot = 0.f;
#pragma unroll
        for (int i = 0; i < 8; i++) tot += sred[i];
        g_invr[row] = 1.0f / tot;  // tot >= 1 (diagonal term is exp(0)=1)
    }
}

// ---------------- GEMM2: xneg = [E * (invr_i + invr_k)] @ x ----------------
__global__ void __launch_bounds__(256, 2) gemm2_kernel(const float* __restrict__ x) {
    int bx = blockIdx.x;  // 0..3 (column tiles of D=512)
    int by = blockIdx.y;  // 0..63 (row tiles)

    __shared__ float As[16][128];
    __shared__ float Bs[16][128];

    int t = threadIdx.x;
    int tx = t & 15, ty = t >> 4;
    int lrow = t >> 1;
    int lkb = (t & 1) * 8;
    int gi = by * 128 + lrow;
    float ri = g_invr[gi];
    const float* eptr = g_E + (size_t)gi * NR + lkb;

    int brow = t >> 4;          // 0..15 (k within tile)
    int bcol = (t & 15) * 8;    // 0..120
    const float* xptr = x + bx * 128 + bcol;

    float acc[8][8];
#pragma unroll
    for (int i = 0; i < 8; i++)
#pragma unroll
        for (int j = 0; j < 8; j++) acc[i][j] = 0.f;

    for (int k0 = 0; k0 < NR; k0 += 16) {
        float4 e0 = *(const float4*)(eptr + k0);
        float4 e1 = *(const float4*)(eptr + k0 + 4);
        // fold the dual-softmax weight into the A operand
        As[lkb + 0][lrow] = e0.x * (ri + __ldg(&g_invr[k0 + lkb + 0]));
        As[lkb + 1][lrow] = e0.y * (ri + __ldg(&g_invr[k0 + lkb + 1]));
        As[lkb + 2][lrow] = e0.z * (ri + __ldg(&g_invr[k0 + lkb + 2]));
        As[lkb + 3][lrow] = e0.w * (ri + __ldg(&g_invr[k0 + lkb + 3]));
        As[lkb + 4][lrow] = e1.x * (ri + __ldg(&g_invr[k0 + lkb + 4]));
        As[lkb + 5][lrow] = e1.y * (ri + __ldg(&g_invr[k0 + lkb + 5]));
        As[lkb + 6][lrow] = e1.z * (ri + __ldg(&g_invr[k0 + lkb + 6]));
        As[lkb + 7][lrow] = e1.w * (ri + __ldg(&g_invr[k0 + lkb + 7]));

        float4 xa = *(const float4*)(xptr + (size_t)(k0 + brow) * D);
        float4 xb = *(const float4*)(xptr + (size_t)(k0 + brow) * D + 4);
        Bs[brow][bcol + 0] = xa.x; Bs[brow][bcol + 1] = xa.y;
        Bs[brow][bcol + 2] = xa.z; Bs[brow][bcol + 3] = xa.w;
        Bs[brow][bcol + 4] = xb.x; Bs[brow][bcol + 5] = xb.y;
        Bs[brow][bcol + 6] = xb.z; Bs[brow][bcol + 7] = xb.w;
        __syncthreads();
#pragma unroll
        for (int kk = 0; kk < 16; kk++) {
            float4 xa0 = *(const float4*)&As[kk][ty * 8];
            float4 xa1 = *(const float4*)&As[kk][ty * 8 + 4];
            float4 yb0 = *(const float4*)&Bs[kk][tx * 8];
            float4 yb1 = *(const float4*)&Bs[kk][tx * 8 + 4];
            float av[8] = {xa0.x, xa0.y, xa0.z, xa0.w, xa1.x, xa1.y, xa1.z, xa1.w};
            float bv[8] = {yb0.x, yb0.y, yb0.z, yb0.w, yb1.x, yb1.y, yb1.z, yb1.w};
#pragma unroll
            for (int i = 0; i < 8; i++)
#pragma unroll
                for (int j = 0; j < 8; j++)
                    acc[i][j] = fmaf(av[i], bv[j], acc[i][j]);
        }
        __syncthreads();
    }

    int gr0 = by * 128 + ty * 8;
    int gc0 = bx * 128 + tx * 8;
#pragma unroll
    for (int i = 0; i < 8; i++) {
        float4 w0 = make_float4(acc[i][0], acc[i][1], acc[i][2], acc[i][3]);
        float4 w1 = make_float4(acc[i][4], acc[i][5], acc[i][6], acc[i][7]);
        *(float4*)(g_xneg + (size_t)(gr0 + i) * D + gc0)     = w0;
        *(float4*)(g_xneg + (size_t)(gr0 + i) * D + gc0 + 4) = w1;
    }
}

// ---------------- y = x - SCALE*xneg, LayerNorm ----------------
__global__ void ln_kernel(const float* __restrict__ x, const float* __restrict__ gamma,
                          const float* __restrict__ beta, float* __restrict__ out) {
    __shared__ float s1[4], s2[4];
    int row = blockIdx.x, t = threadIdx.x;  // 128 threads
    float4 xv = ((const float4*)(x + (size_t)row * D))[t];
    float4 nv = ((const float4*)(g_xneg + (size_t)row * D))[t];
    float4 y = make_float4(xv.x - SCALE * nv.x, xv.y - SCALE * nv.y,
                           xv.z - SCALE * nv.z, xv.w - SCALE * nv.w);
    float s = y.x + y.y + y.z + y.w;
    float q = y.x * y.x + y.y * y.y + y.z * y.z + y.w * y.w;
    s = warpReduceSum(s);
    q = warpReduceSum(q);
    if ((t & 31) == 0) { s1[t >> 5] = s; s2[t >> 5] = q; }
    __syncthreads();
    float sum = s1[0] + s1[1] + s1[2] + s1[3];
    float sq  = s2[0] + s2[1] + s2[2] + s2[3];
    float mean = sum * (1.0f / D);
    float var = sq * (1.0f / D) - mean * mean;
    float rstd = rsqrtf(var + 1e-6f);
    float4 g = ((const float4*)gamma)[t];
    float4 b = ((const float4*)beta)[t];
    float4 o;
    o.x = (y.x - mean) * rstd * g.x + b.x;
    o.y = (y.y - mean) * rstd * g.y + b.y;
    o.z = (y.z - mean) * rstd * g.z + b.z;
    o.w = (y.w - mean) * rstd * g.w + b.w;
    ((float4*)out)[(size_t)row * (D / 4) + t] = o;
}

extern "C" void kernel_launch(void* const* d_in, const int* in_sizes, int n_in,
                              void* d_out, int out_size) {
    const float* x     = (const float*)d_in[0];
    const float* gamma = (const float*)d_in[1];
    const float* beta  = (const float*)d_in[2];
    float* out = (float*)d_out;

    prep_kernel<<<NR, 128>>>(x);

    dim3 g1(NR / 128, NR / 128);
    gemm1_kernel<<<g1, 256>>>();

    rowsum_kernel<<<NR, 256>>>();

    dim3 g2(D / 128, NR / 128);
    gemm2_kernel<<<g2, 256>>>(x);

    ln_kernel<<<NR, 128>>>(x, gamma, beta, out);
}

// round 3
// speedup vs baseline: 2.0495x; 2.0495x over previous
#include <cuda_runtime.h>
#include <math.h>
#include <stdint.h>

#define NR 8192
#define D  512
#define SCALEF 0.1f

// Scratch (allocation-free rule: __device__ globals)
__device__ float g_E[(size_t)NR * NR];      // 256 MB: E = exp(sim - 1)
__device__ float g_xn[(size_t)NR * D];      // 16 MB: row-normalized x
__device__ float g_xneg[(size_t)NR * D];    // 16 MB
__device__ float g_invr[NR];                // 32 KB

__device__ __forceinline__ float warpReduceSum(float v) {
#pragma unroll
    for (int o = 16; o > 0; o >>= 1) v += __shfl_xor_sync(0xffffffffu, v, o);
    return v;
}

__device__ __forceinline__ uint32_t f2tf(float f) {
    uint32_t u;
    asm("cvt.rna.tf32.f32 %0, %1;" : "=r"(u) : "f"(f));
    return u;
}

__device__ __forceinline__ void mma_tf32(float* c, uint32_t a0, uint32_t a1, uint32_t a2,
                                         uint32_t a3, uint32_t b0, uint32_t b1) {
    asm volatile(
        "mma.sync.aligned.m16n8k8.row.col.f32.tf32.tf32.f32 "
        "{%0,%1,%2,%3}, {%4,%5,%6,%7}, {%8,%9}, {%0,%1,%2,%3};"
        : "+f"(c[0]), "+f"(c[1]), "+f"(c[2]), "+f"(c[3])
        : "r"(a0), "r"(a1), "r"(a2), "r"(a3), "r"(b0), "r"(b1));
}

// ---------------- prep: L2-normalize rows ----------------
__global__ void prep_kernel(const float* __restrict__ x) {
    __shared__ float sred[4];
    int row = blockIdx.x;
    int t = threadIdx.x;  // 128 threads
    float4 a = ((const float4*)(x + (size_t)row * D))[t];
    float ss = a.x * a.x + a.y * a.y + a.z * a.z + a.w * a.w;
    ss = warpReduceSum(ss);
    if ((t & 31) == 0) sred[t >> 5] = ss;
    __syncthreads();
    float tot = sred[0] + sred[1] + sred[2] + sred[3];
    float inv = 1.0f / fmaxf(sqrtf(tot), 1e-12f);
    float4 o = make_float4(a.x * inv, a.y * inv, a.z * inv, a.w * inv);
    ((float4*)g_xn)[(size_t)row * (D / 4) + t] = o;
}

// ============== GEMM1: E = exp(xn @ xn^T - 1), upper blocks + mirror ==============
// smem (uint32 words): stage s at s*9216: A[128][36] then B[128][36]
// epilogue reuses smem as float[128*129]
#define G1_SMEM_BYTES (2 * 9216 * 4)

__global__ void __launch_bounds__(256) gemm1_kernel() {
    int bj = blockIdx.x, bi = blockIdx.y;
    if (bi > bj) return;
    const int I0 = bi * 128, J0 = bj * 128;

    extern __shared__ uint32_t su[];
    int t = threadIdx.x, wid = t >> 5, lane = t & 31;
    int g = lane >> 2, tq = lane & 3;
    int warpM = (wid >> 2) * 64, warpN = (wid & 3) * 32;

    int ar = t >> 1, ah = (t & 1) * 16;
    const float* aG = g_xn + (size_t)(I0 + ar) * D + ah;
    const float* bG = g_xn + (size_t)(J0 + ar) * D + ah;

    float acc[4][4][4];
#pragma unroll
    for (int i = 0; i < 4; i++)
#pragma unroll
        for (int j = 0; j < 4; j++)
#pragma unroll
            for (int q = 0; q < 4; q++) acc[i][j][q] = 0.f;

    float4 pa[4], pb[4];
    auto ldg_chunk = [&](int k0) {
#pragma unroll
        for (int q = 0; q < 4; q++) {
            pa[q] = ((const float4*)(aG + k0))[q];
            pb[q] = ((const float4*)(bG + k0))[q];
        }
    };
    auto sts_chunk = [&](int stage) {
        uint32_t* dA = su + stage * 9216 + ar * 36 + ah;
        uint32_t* dB = su + stage * 9216 + 4608 + ar * 36 + ah;
#pragma unroll
        for (int q = 0; q < 4; q++) {
            uint4 va = make_uint4(f2tf(pa[q].x), f2tf(pa[q].y), f2tf(pa[q].z), f2tf(pa[q].w));
            uint4 vb = make_uint4(f2tf(pb[q].x), f2tf(pb[q].y), f2tf(pb[q].z), f2tf(pb[q].w));
            *(uint4*)(dA + q * 4) = va;
            *(uint4*)(dB + q * 4) = vb;
        }
    };

    const int C = D / 32;  // 16
    ldg_chunk(0);
    sts_chunk(0);
    ldg_chunk(32);
    __syncthreads();

    for (int c = 0; c < C; c++) {
        if (c + 1 < C) sts_chunk((c + 1) & 1);
        if (c + 2 < C) ldg_chunk((c + 2) * 32);
        const uint32_t* sA = su + (c & 1) * 9216;
        const uint32_t* sB = sA + 4608;
#pragma unroll
        for (int s = 0; s < 4; s++) {
            uint32_t af[4][4], bf[4][2];
#pragma unroll
            for (int i = 0; i < 4; i++) {
                int base = (warpM + i * 16 + g) * 36 + 8 * s + tq;
                af[i][0] = sA[base];
                af[i][1] = sA[base + 8 * 36];
                af[i][2] = sA[base + 4];
                af[i][3] = sA[base + 8 * 36 + 4];
            }
#pragma unroll
            for (int j = 0; j < 4; j++) {
                int nb = (warpN + j * 8 + g) * 36 + 8 * s + tq;
                bf[j][0] = sB[nb];
                bf[j][1] = sB[nb + 4];
            }
#pragma unroll
            for (int i = 0; i < 4; i++)
#pragma unroll
                for (int j = 0; j < 4; j++)
                    mma_tf32(acc[i][j], af[i][0], af[i][1], af[i][2], af[i][3],
                             bf[j][0], bf[j][1]);
        }
        __syncthreads();
    }

    // epilogue: exp(s-1) -> smem[128][129] -> coalesced natural + mirror writes
    float* eb = (float*)su;
#pragma unroll
    for (int i = 0; i < 4; i++)
#pragma unroll
        for (int j = 0; j < 4; j++) {
            int r0 = warpM + i * 16 + g;
            int c0 = warpN + j * 8 + 2 * tq;
            eb[r0 * 129 + c0]           = __expf(acc[i][j][0] - 1.0f);
            eb[r0 * 129 + c0 + 1]       = __expf(acc[i][j][1] - 1.0f);
            eb[(r0 + 8) * 129 + c0]     = __expf(acc[i][j][2] - 1.0f);
            eb[(r0 + 8) * 129 + c0 + 1] = __expf(acc[i][j][3] - 1.0f);
        }
    __syncthreads();

    {
        int r = t >> 1, h = (t & 1) * 64;
        float* dst = g_E + (size_t)(I0 + r) * NR + J0 + h;
        const float* src = eb + r * 129 + h;
#pragma unroll
        for (int q = 0; q < 16; q++) {
            float4 v = make_float4(src[q * 4], src[q * 4 + 1], src[q * 4 + 2], src[q * 4 + 3]);
            ((float4*)dst)[q] = v;
        }
        // mirror (E symmetric); diagonal blocks write identical values twice
        int cc = t >> 1;
        float* dst2 = g_E + (size_t)(J0 + cc) * NR + I0 + h;
#pragma unroll
        for (int q = 0; q < 16; q++) {
            float4 v = make_float4(eb[(h + q * 4 + 0) * 129 + cc], eb[(h + q * 4 + 1) * 129 + cc],
                                   eb[(h + q * 4 + 2) * 129 + cc], eb[(h + q * 4 + 3) * 129 + cc]);
            ((float4*)dst2)[q] = v;
        }
    }
}

// ---------------- row sums of E -> invr (deterministic) ----------------
__global__ void rowsum_kernel() {
    __shared__ float sred[8];
    int row = blockIdx.x, t = threadIdx.x;  // 256 threads
    const float4* e = (const float4*)(g_E + (size_t)row * NR);
    float s = 0.f;
#pragma unroll
    for (int i = 0; i < 8; i++) {
        float4 v = e[t + 256 * i];
        s += (v.x + v.y) + (v.z + v.w);
    }
    s = warpReduceSum(s);
    if ((t & 31) == 0) sred[t >> 5] = s;
    __syncthreads();
    if (t == 0) {
        float tot = 0.f;
#pragma unroll
        for (int i = 0; i < 8; i++) tot += sred[i];
        g_invr[row] = 1.0f / tot;
    }
}

// ============== GEMM2: xneg = [E*(invr_i+invr_k)] @ x ==============
// smem words: stage s at s*8960: A[128][36] then B[32][136]
#define G2_SMEM_BYTES (2 * 8960 * 4)

__global__ void __launch_bounds__(256) gemm2_kernel(const float* __restrict__ x) {
    const int n0 = blockIdx.x * 128;  // 0..3
    const int I0 = blockIdx.y * 128;  // 0..63

    extern __shared__ uint32_t su[];
    int t = threadIdx.x, wid = t >> 5, lane = t & 31;
    int g = lane >> 2, tq = lane & 3;
    int warpM = (wid >> 2) * 64, warpN = (wid & 3) * 32;

    int ar = t >> 1, ah = (t & 1) * 16;
    const float ri = g_invr[I0 + ar];
    const float* aG = g_E + (size_t)(I0 + ar) * NR + ah;
    int br = t >> 3, bs = (t & 7) * 16;
    const float* bG = x + (size_t)br * D + n0 + bs;

    float acc[4][4][4];
#pragma unroll
    for (int i = 0; i < 4; i++)
#pragma unroll
        for (int j = 0; j < 4; j++)
#pragma unroll
            for (int q = 0; q < 4; q++) acc[i][j][q] = 0.f;

    float4 pa[4], pb[4];
    auto ldg_chunk = [&](int k0) {
#pragma unroll
        for (int q = 0; q < 4; q++) {
            pa[q] = ((const float4*)(aG + k0))[q];
            pb[q] = ((const float4*)(bG + (size_t)k0 * D))[q];
        }
    };
    auto sts_chunk = [&](int stage, int kSts) {
        uint32_t* dA = su + stage * 8960 + ar * 36 + ah;
        uint32_t* dB = su + stage * 8960 + 4608 + br * 136 + bs;
        const float4* rk = (const float4*)(g_invr + kSts + ah);
#pragma unroll
        for (int q = 0; q < 4; q++) {
            float4 rv = __ldg(&rk[q]);
            uint4 va = make_uint4(f2tf(pa[q].x * (ri + rv.x)), f2tf(pa[q].y * (ri + rv.y)),
                                  f2tf(pa[q].z * (ri + rv.z)), f2tf(pa[q].w * (ri + rv.w)));
            uint4 vb = make_uint4(f2tf(pb[q].x), f2tf(pb[q].y), f2tf(pb[q].z), f2tf(pb[q].w));
            *(uint4*)(dA + q * 4) = va;
            *(uint4*)(dB + q * 4) = vb;
        }
    };

    const int C = NR / 32;  // 256
    ldg_chunk(0);
    sts_chunk(0, 0);
    ldg_chunk(32);
    __syncthreads();

    for (int c = 0; c < C; c++) {
        if (c + 1 < C) sts_chunk((c + 1) & 1, (c + 1) * 32);
        if (c + 2 < C) ldg_chunk((c + 2) * 32);
        const uint32_t* sA = su + (c & 1) * 8960;
        const uint32_t* sB = sA + 4608;
#pragma unroll
        for (int s = 0; s < 4; s++) {
            uint32_t af[4][4], bf[4][2];
#pragma unroll
            for (int i = 0; i < 4; i++) {
                int base = (warpM + i * 16 + g) * 36 + 8 * s + tq;
                af[i][0] = sA[base];
                af[i][1] = sA[base + 8 * 36];
                af[i][2] = sA[base + 4];
                af[i][3] = sA[base + 8 * 36 + 4];
            }
#pragma unroll
            for (int j = 0; j < 4; j++) {
                int nb = warpN + j * 8 + g;
                bf[j][0] = sB[(8 * s + tq) * 136 + nb];
                bf[j][1] = sB[(8 * s + tq + 4) * 136 + nb];
            }
#pragma unroll
            for (int i = 0; i < 4; i++)
#pragma unroll
                for (int j = 0; j < 4; j++)
                    mma_tf32(acc[i][j], af[i][0], af[i][1], af[i][2], af[i][3],
                             bf[j][0], bf[j][1]);
        }
        __syncthreads();
    }

    // epilogue: direct float2 stores
#pragma unroll
    for (int i = 0; i < 4; i++)
#pragma unroll
        for (int j = 0; j < 4; j++) {
            int r0 = I0 + warpM + i * 16 + g;
            int c0 = n0 + warpN + j * 8 + 2 * tq;
            *(float2*)(g_xneg + (size_t)r0 * D + c0)       = make_float2(acc[i][j][0], acc[i][j][1]);
            *(float2*)(g_xneg + (size_t)(r0 + 8) * D + c0) = make_float2(acc[i][j][2], acc[i][j][3]);
        }
}

// ---------------- y = x - SCALE*xneg, LayerNorm ----------------
__global__ void ln_kernel(const float* __restrict__ x, const float* __restrict__ gamma,
                          const float* __restrict__ beta, float* __restrict__ out) {
    __shared__ float s1[4], s2[4];
    int row = blockIdx.x, t = threadIdx.x;  // 128 threads
    float4 xv = ((const float4*)(x + (size_t)row * D))[t];
    float4 nv = ((const float4*)(g_xneg + (size_t)row * D))[t];
    float4 y = make_float4(xv.x - SCALEF * nv.x, xv.y - SCALEF * nv.y,
                           xv.z - SCALEF * nv.z, xv.w - SCALEF * nv.w);
    float s = y.x + y.y + y.z + y.w;
    float q = y.x * y.x + y.y * y.y + y.z * y.z + y.w * y.w;
    s = warpReduceSum(s);
    q = warpReduceSum(q);
    if ((t & 31) == 0) { s1[t >> 5] = s; s2[t >> 5] = q; }
    __syncthreads();
    float sum = s1[0] + s1[1] + s1[2] + s1[3];
    float sq  = s2[0] + s2[1] + s2[2] + s2[3];
    float mean = sum * (1.0f / D);
    float var = sq * (1.0f / D) - mean * mean;
    float rstd = rsqrtf(var + 1e-6f);
    float4 gm = ((const float4*)gamma)[t];
    float4 b = ((const float4*)beta)[t];
    float4 o;
    o.x = (y.x - mean) * rstd * gm.x + b.x;
    o.y = (y.y - mean) * rstd * gm.y + b.y;
    o.z = (y.z - mean) * rstd * gm.z + b.z;
    o.w = (y.w - mean) * rstd * gm.w + b.w;
    ((float4*)out)[(size_t)row * (D / 4) + t] = o;
}

extern "C" void kernel_launch(void* const* d_in, const int* in_sizes, int n_in,
                              void* d_out, int out_size) {
    const float* x     = (const float*)d_in[0];
    const float* gamma = (const float*)d_in[1];
    const float* beta  = (const float*)d_in[2];
    float* out = (float*)d_out;

    cudaFuncSetAttribute(gemm1_kernel, cudaFuncAttributeMaxDynamicSharedMemorySize, G1_SMEM_BYTES);
    cudaFuncSetAttribute(gemm2_kernel, cudaFuncAttributeMaxDynamicSharedMemorySize, G2_SMEM_BYTES);

    prep_kernel<<<NR, 128>>>(x);
    gemm1_kernel<<<dim3(64, 64), 256, G1_SMEM_BYTES>>>();
    rowsum_kernel<<<NR, 256>>>();
    gemm2_kernel<<<dim3(4, 64), 256, G2_SMEM_BYTES>>>(x);
    ln_kernel<<<NR, 128>>>(x, gamma, beta, out);
}

// round 4
// speedup vs baseline: 2.1213x; 1.0350x over previous
#include <cuda_runtime.h>
#include <math.h>
#include <stdint.h>

#define NR 8192
#define D  512
#define SCALEF 0.1f

// Scratch (allocation-free rule: __device__ globals)
__device__ float g_E[(size_t)NR * NR];      // 256 MB: E = exp(sim-1), k-permuted columns
__device__ float g_xn[(size_t)NR * D];      // 16 MB: normalized x, k-permuted features
__device__ float g_xt[(size_t)D * NR];      // 16 MB: x^T [512][8192], k-permuted columns
__device__ float g_xneg[(size_t)NR * D];    // 16 MB
__device__ float g_invr[NR];                // natural order
__device__ float g_invr_p[NR];              // k-permuted order

// stored position p (within 8-group) holds logical element l(p) = (p>>1) + 4*(p&1)
__device__ __host__ __forceinline__ int lperm(int p) { return (p >> 1) + 4 * (p & 1); }

#define ROWW 40                 // smem row stride in words (160B: 16B-aligned, conflict-free)
#define TILEW (128 * ROWW)      // 5120 words per operand tile
#define STAGEW (2 * TILEW)      // A + B per stage
#define SMEM_BYTES (2 * STAGEW * 4)  // 81920

__device__ __forceinline__ float warpReduceSum(float v) {
#pragma unroll
    for (int o = 16; o > 0; o >>= 1) v += __shfl_xor_sync(0xffffffffu, v, o);
    return v;
}
__device__ __forceinline__ uint32_t smem_u32(const void* p) {
    uint32_t a;
    asm("{ .reg .u64 t; cvta.to.shared.u64 t, %1; cvt.u32.u64 %0, t; }" : "=r"(a) : "l"(p));
    return a;
}
__device__ __forceinline__ void cp16(uint32_t s, const void* g) {
    asm volatile("cp.async.cg.shared.global [%0], [%1], 16;" :: "r"(s), "l"(g));
}
#define CP_COMMIT() asm volatile("cp.async.commit_group;")
#define CP_WAIT1()  asm volatile("cp.async.wait_group 1;")
#define CP_WAIT0()  asm volatile("cp.async.wait_group 0;")

__device__ __forceinline__ void mma_tf32(float* c, uint32_t a0, uint32_t a1, uint32_t a2,
                                         uint32_t a3, uint32_t b0, uint32_t b1) {
    asm volatile(
        "mma.sync.aligned.m16n8k8.row.col.f32.tf32.tf32.f32 "
        "{%0,%1,%2,%3}, {%4,%5,%6,%7}, {%8,%9}, {%0,%1,%2,%3};"
        : "+f"(c[0]), "+f"(c[1]), "+f"(c[2]), "+f"(c[3])
        : "r"(a0), "r"(a1), "r"(a2), "r"(a3), "r"(b0), "r"(b1));
}

// ---------------- prep: L2-normalize rows, write k-permuted ----------------
__global__ void prep_kernel(const float* __restrict__ x) {
    __shared__ float sred[4];
    int row = blockIdx.x;
    int t = threadIdx.x;  // 128 threads
    float4 a = ((const float4*)(x + (size_t)row * D))[t];
    float ss = a.x * a.x + a.y * a.y + a.z * a.z + a.w * a.w;
    ss = warpReduceSum(ss);
    if ((t & 31) == 0) sred[t >> 5] = ss;
    __syncthreads();
    float tot = sred[0] + sred[1] + sred[2] + sred[3];
    float inv = 1.0f / fmaxf(sqrtf(tot), 1e-12f);
    // features 4t..4t+3 -> permuted positions: base + 2*(l&3) + (l>>2)
    float v[4] = {a.x * inv, a.y * inv, a.z * inv, a.w * inv};
    float* dst = g_xn + (size_t)row * D;
#pragma unroll
    for (int e = 0; e < 4; e++) {
        int f = 4 * t + e;
        int p = (f & ~7) | (((f & 3) << 1) | ((f >> 2) & 1));
        dst[p] = v[e];
    }
}

// ---------------- transpose x -> g_xt [512][8192], k-permuted columns ----------------
__global__ void transpose_kernel(const float* __restrict__ x) {
    __shared__ float tl[32][33];
    int k0 = blockIdx.x * 32, n0 = blockIdx.y * 32;
    int tx = threadIdx.x, ty = threadIdx.y;  // 32 x 8
#pragma unroll
    for (int r = 0; r < 32; r += 8)
        tl[ty + r][tx] = x[(size_t)(k0 + ty + r) * D + n0 + tx];
    __syncthreads();
    int ltx = (tx & ~7) | lperm(tx & 7);  // stored col tx holds logical row k0+ltx
#pragma unroll
    for (int r = 0; r < 32; r += 8)
        g_xt[(size_t)(n0 + ty + r) * NR + k0 + tx] = tl[ltx][ty + r];
}

// ============== GEMM1: E = exp(xn @ xn^T - 1), triangular grid + mirror ==============
__global__ void __launch_bounds__(256, 2) gemm1_kernel() {
    // decode triangular index: bi <= bj
    int kid = blockIdx.x;
    int bj = (int)((sqrtf(8.0f * (float)kid + 1.0f) - 1.0f) * 0.5f);
    while ((bj + 1) * (bj + 2) / 2 <= kid) bj++;
    while (bj * (bj + 1) / 2 > kid) bj--;
    int bi = kid - bj * (bj + 1) / 2;
    const int I0 = bi * 128, J0 = bj * 128;

    extern __shared__ uint32_t su[];
    uint32_t sbase = smem_u32(su);
    int t = threadIdx.x, wid = t >> 5, lane = t & 31;
    int g = lane >> 2, tq = lane & 3;
    int warpM = (wid >> 2) * 64, warpN = (wid & 3) * 32;

    int r = t >> 1, h = t & 1;
    const float* aG = g_xn + (size_t)(I0 + r) * D + h * 16;
    const float* bG = g_xn + (size_t)(J0 + r) * D + h * 16;
    uint32_t dstA = sbase + (uint32_t)(r * ROWW + h * 16) * 4;
    uint32_t dstB = dstA + TILEW * 4;

    auto copy_stage = [&](int stage, int k0) {
        uint32_t off = (uint32_t)(stage * STAGEW) * 4;
#pragma unroll
        for (int q = 0; q < 4; q++) {
            cp16(dstA + off + q * 16, aG + k0 + q * 4);
            cp16(dstB + off + q * 16, bG + k0 + q * 4);
        }
        CP_COMMIT();
    };

    float acc[4][4][4];
#pragma unroll
    for (int i = 0; i < 4; i++)
#pragma unroll
        for (int j = 0; j < 4; j++)
#pragma unroll
            for (int q = 0; q < 4; q++) acc[i][j][q] = 0.f;

    const int C = D / 32;  // 16
    copy_stage(0, 0);
    copy_stage(1, 32);
    CP_WAIT1();
    __syncthreads();

    for (int c = 0; c < C; c++) {
        const uint32_t* sA = su + (c & 1) * STAGEW;
        const uint32_t* sB = sA + TILEW;
#pragma unroll
        for (int s = 0; s < 4; s++) {
            uint32_t af[4][4], bf[4][2];
#pragma unroll
            for (int i = 0; i < 4; i++) {
                const uint32_t* pa = sA + (warpM + i * 16 + g) * ROWW + 8 * s + 2 * tq;
                uint2 lo = *(const uint2*)pa;            // (a0, a2)
                uint2 hi = *(const uint2*)(pa + 8 * ROWW);  // (a1, a3)
                af[i][0] = lo.x; af[i][1] = hi.x; af[i][2] = lo.y; af[i][3] = hi.y;
            }
#pragma unroll
            for (int j = 0; j < 4; j++) {
                uint2 b = *(const uint2*)(sB + (warpN + j * 8 + g) * ROWW + 8 * s + 2 * tq);
                bf[j][0] = b.x; bf[j][1] = b.y;
            }
#pragma unroll
            for (int i = 0; i < 4; i++)
#pragma unroll
                for (int j = 0; j < 4; j++)
                    mma_tf32(acc[i][j], af[i][0], af[i][1], af[i][2], af[i][3],
                             bf[j][0], bf[j][1]);
        }
        __syncthreads();
        if (c + 2 < C) { copy_stage(c & 1, (c + 2) * 32); CP_WAIT1(); }
        else CP_WAIT0();
        __syncthreads();
    }

    // epilogue: exp(s-1) -> smem[128][129] (logical cols) -> permuted coalesced writes
    float* eb = (float*)su;
#pragma unroll
    for (int i = 0; i < 4; i++)
#pragma unroll
        for (int j = 0; j < 4; j++) {
            int r0 = warpM + i * 16 + g;
            int c0 = warpN + j * 8 + 2 * tq;
            eb[r0 * 129 + c0]           = __expf(acc[i][j][0] - 1.0f);
            eb[r0 * 129 + c0 + 1]       = __expf(acc[i][j][1] - 1.0f);
            eb[(r0 + 8) * 129 + c0]     = __expf(acc[i][j][2] - 1.0f);
            eb[(r0 + 8) * 129 + c0 + 1] = __expf(acc[i][j][3] - 1.0f);
        }
    __syncthreads();

    {
        int rr = t >> 1, hh = (t & 1) * 64;
        // natural tile: E[I0+rr][J0 + stored p] = eb[rr][logical(p)]
        float* dst = g_E + (size_t)(I0 + rr) * NR + J0 + hh;
        const float* src = eb + rr * 129;
#pragma unroll
        for (int q = 0; q < 16; q++) {
            int p0 = hh + 4 * q;
            float4 v;
            v.x = src[(p0 & ~7) | lperm(p0 & 7)];
            v.y = src[((p0 + 1) & ~7) | lperm((p0 + 1) & 7)];
            v.z = src[((p0 + 2) & ~7) | lperm((p0 + 2) & 7)];
            v.w = src[((p0 + 3) & ~7) | lperm((p0 + 3) & 7)];
            ((float4*)dst)[q] = v;
        }
        // mirror: E[J0+rr][I0 + stored p] = eb[logical(p)][rr]
        float* dst2 = g_E + (size_t)(J0 + rr) * NR + I0 + hh;
#pragma unroll
        for (int q = 0; q < 16; q++) {
            int p0 = hh + 4 * q;
            float4 v;
            v.x = eb[((p0 & ~7) | lperm(p0 & 7)) * 129 + rr];
            v.y = eb[(((p0 + 1) & ~7) | lperm((p0 + 1) & 7)) * 129 + rr];
            v.z = eb[(((p0 + 2) & ~7) | lperm((p0 + 2) & 7)) * 129 + rr];
            v.w = eb[(((p0 + 3) & ~7) | lperm((p0 + 3) & 7)) * 129 + rr];
            ((float4*)dst2)[q] = v;
        }
    }
}

// ---------------- row sums of E -> invr ----------------
__global__ void rowsum_kernel() {
    __shared__ float sred[8];
    int row = blockIdx.x, t = threadIdx.x;  // 256 threads
    const float4* e = (const float4*)(g_E + (size_t)row * NR);
    float s = 0.f;
#pragma unroll
    for (int i = 0; i < 8; i++) {
        float4 v = e[t + 256 * i];
        s += (v.x + v.y) + (v.z + v.w);
    }
    s = warpReduceSum(s);
    if ((t & 31) == 0) sred[t >> 5] = s;
    __syncthreads();
    if (t == 0) {
        float tot = 0.f;
#pragma unroll
        for (int i = 0; i < 8; i++) tot += sred[i];
        g_invr[row] = 1.0f / tot;
    }
}

// ---------------- permuted copy of invr ----------------
__global__ void permute_invr_kernel() {
    int i = blockIdx.x * 256 + threadIdx.x;
    g_invr_p[i] = g_invr[(i & ~7) | lperm(i & 7)];
}

// ============== GEMM2: xneg = [E*(invr_i+invr_k)] @ x ==============
__global__ void __launch_bounds__(256, 2) gemm2_kernel() {
    const int n0 = blockIdx.x * 128;  // 0..3
    const int I0 = blockIdx.y * 128;  // 0..63

    extern __shared__ uint32_t su[];
    uint32_t sbase = smem_u32(su);
    int t = threadIdx.x, wid = t >> 5, lane = t & 31;
    int g = lane >> 2, tq = lane & 3;
    int warpM = (wid >> 2) * 64, warpN = (wid & 3) * 32;

    int r = t >> 1, h = t & 1;
    const float ri = g_invr[I0 + r];
    const float* aG = g_E + (size_t)(I0 + r) * NR + h * 16;   // k-permuted stored order
    const float* bG = g_xt + (size_t)(n0 + r) * NR + h * 16;  // k-permuted stored order
    uint32_t stsA = smem_u32(su + r * ROWW + h * 16);
    uint32_t dstB = sbase + (uint32_t)(TILEW + r * ROWW + h * 16) * 4;

    float4 pa[4];
    auto ldgA = [&](int k0) {
#pragma unroll
        for (int q = 0; q < 4; q++) pa[q] = ((const float4*)(aG + k0))[q];
    };
    auto stsA_f = [&](int stage, int k0) {
        const float4* rk = (const float4*)(g_invr_p + k0 + h * 16);
        uint32_t dst = stsA + (uint32_t)(stage * STAGEW) * 4;
#pragma unroll
        for (int q = 0; q < 4; q++) {
            float4 rv = __ldg(&rk[q]);
            float4 v = make_float4(pa[q].x * (ri + rv.x), pa[q].y * (ri + rv.y),
                                   pa[q].z * (ri + rv.z), pa[q].w * (ri + rv.w));
            asm volatile("st.shared.v4.b32 [%0], {%1,%2,%3,%4};"
                         :: "r"(dst + q * 16), "f"(v.x), "f"(v.y), "f"(v.z), "f"(v.w));
        }
    };
    auto cpB = [&](int stage, int k0) {
        uint32_t off = (uint32_t)(stage * STAGEW) * 4;
#pragma unroll
        for (int q = 0; q < 4; q++)
            cp16(dstB + off + q * 16, bG + k0 + q * 4);
        CP_COMMIT();
    };

    float acc[4][4][4];
#pragma unroll
    for (int i = 0; i < 4; i++)
#pragma unroll
        for (int j = 0; j < 4; j++)
#pragma unroll
            for (int q = 0; q < 4; q++) acc[i][j][q] = 0.f;

    const int C = NR / 32;  // 256
    ldgA(0); stsA_f(0, 0); cpB(0, 0);
    ldgA(32);
    cpB(1, 32);
    CP_WAIT1();
    __syncthreads();

    for (int c = 0; c < C; c++) {
        if (c + 1 < C) stsA_f((c + 1) & 1, (c + 1) * 32);
        if (c + 2 < C) ldgA((c + 2) * 32);
        const uint32_t* sA = su + (c & 1) * STAGEW;
        const uint32_t* sB = sA + TILEW;
#pragma unroll
        for (int s = 0; s < 4; s++) {
            uint32_t af[4][4], bf[4][2];
#pragma unroll
            for (int i = 0; i < 4; i++) {
                const uint32_t* p = sA + (warpM + i * 16 + g) * ROWW + 8 * s + 2 * tq;
                uint2 lo = *(const uint2*)p;
                uint2 hi = *(const uint2*)(p + 8 * ROWW);
                af[i][0] = lo.x; af[i][1] = hi.x; af[i][2] = lo.y; af[i][3] = hi.y;
            }
#pragma unroll
            for (int j = 0; j < 4; j++) {
                uint2 b = *(const uint2*)(sB + (warpN + j * 8 + g) * ROWW + 8 * s + 2 * tq);
                bf[j][0] = b.x; bf[j][1] = b.y;
            }
#pragma unroll
            for (int i = 0; i < 4; i++)
#pragma unroll
                for (int j = 0; j < 4; j++)
                    mma_tf32(acc[i][j], af[i][0], af[i][1], af[i][2], af[i][3],
                             bf[j][0], bf[j][1]);
        }
        __syncthreads();
        if (c + 2 < C) { cpB(c & 1, (c + 2) * 32); CP_WAIT1(); }
        else CP_WAIT0();
        __syncthreads();
    }

    // epilogue: direct float2 stores (n not permuted)
#pragma unroll
    for (int i = 0; i < 4; i++)
#pragma unroll
        for (int j = 0; j < 4; j++) {
            int r0 = I0 + warpM + i * 16 + g;
            int c0 = n0 + warpN + j * 8 + 2 * tq;
            *(float2*)(g_xneg + (size_t)r0 * D + c0)       = make_float2(acc[i][j][0], acc[i][j][1]);
            *(float2*)(g_xneg + (size_t)(r0 + 8) * D + c0) = make_float2(acc[i][j][2], acc[i][j][3]);
        }
}

// ---------------- y = x - SCALE*xneg, LayerNorm ----------------
__global__ void ln_kernel(const float* __restrict__ x, const float* __restrict__ gamma,
                          const float* __restrict__ beta, float* __restrict__ out) {
    __shared__ float s1[4], s2[4];
    int row = blockIdx.x, t = threadIdx.x;  // 128 threads
    float4 xv = ((const float4*)(x + (size_t)row * D))[t];
    float4 nv = ((const float4*)(g_xneg + (size_t)row * D))[t];
    float4 y = make_float4(xv.x - SCALEF * nv.x, xv.y - SCALEF * nv.y,
                           xv.z - SCALEF * nv.z, xv.w - SCALEF * nv.w);
    float s = y.x + y.y + y.z + y.w;
    float q = y.x * y.x + y.y * y.y + y.z * y.z + y.w * y.w;
    s = warpReduceSum(s);
    q = warpReduceSum(q);
    if ((t & 31) == 0) { s1[t >> 5] = s; s2[t >> 5] = q; }
    __syncthreads();
    float sum = s1[0] + s1[1] + s1[2] + s1[3];
    float sq  = s2[0] + s2[1] + s2[2] + s2[3];
    float mean = sum * (1.0f / D);
    float var = sq * (1.0f / D) - mean * mean;
    float rstd = rsqrtf(var + 1e-6f);
    float4 gm = ((const float4*)gamma)[t];
    float4 b = ((const float4*)beta)[t];
    float4 o;
    o.x = (y.x - mean) * rstd * gm.x + b.x;
    o.y = (y.y - mean) * rstd * gm.y + b.y;
    o.z = (y.z - mean) * rstd * gm.z + b.z;
    o.w = (y.w - mean) * rstd * gm.w + b.w;
    ((float4*)out)[(size_t)row * (D / 4) + t] = o;
}

extern "C" void kernel_launch(void* const* d_in, const int* in_sizes, int n_in,
                              void* d_out, int out_size) {
    const float* x     = (const float*)d_in[0];
    const float* gamma = (const float*)d_in[1];
    const float* beta  = (const float*)d_in[2];
    float* out = (float*)d_out;

    cudaFuncSetAttribute(gemm1_kernel, cudaFuncAttributeMaxDynamicSharedMemorySize, SMEM_BYTES);
    cudaFuncSetAttribute(gemm2_kernel, cudaFuncAttributeMaxDynamicSharedMemorySize, SMEM_BYTES);

    prep_kernel<<<NR, 128>>>(x);
    transpose_kernel<<<dim3(NR / 32, D / 32), dim3(32, 8)>>>(x);
    gemm1_kernel<<<64 * 65 / 2, 256, SMEM_BYTES>>>();
    rowsum_kernel<<<NR, 256>>>();
    permute_invr_kernel<<<NR / 256, 256>>>();
    gemm2_kernel<<<dim3(4, 64), 256, SMEM_BYTES>>>();
    ln_kernel<<<NR, 128>>>(x, gamma, beta, out);
}